// round 8
// baseline (speedup 1.0000x reference)
#include <cuda_runtime.h>

// Problem constants
#define B_   2
#define T_   8
#define BT_  16
#define NQ_  128
#define NK_  128
#define DIN_ 64
#define DOUT_ 256
#define DH_  128     // d-values per d-half
#define DC_  64      // d-values per staged chunk
#define KPITCH_ 68   // words per K row (68 % 32 == 4 -> conflict-free LDS.128)

// Device-global scratch (allocation-free per harness rules)
__device__ float g_Q[B_ * NQ_ * DOUT_];       // 256 x 256 fp32
__device__ float g_K[BT_ * NK_ * DOUT_];      // 2048 x 256 fp32
__device__ float g_P[2 * BT_ * NQ_ * NK_];    // partial scores per d-half (2 MB)

__device__ __forceinline__ float ftanh(float x) {
    float r;
    asm("tanh.approx.f32 %0, %1;" : "=f"(r) : "f"(x));
    return r;
}

// ---------------------------------------------------------------------------
// Kernel 1: projections (fp32). Grid = 32 Q + 256 K = 288 blocks (8 rows),
// 2 blocks/SM. W register double-buffered to hide L2 latency.
// ---------------------------------------------------------------------------
__global__ void __launch_bounds__(256, 2) proj_kernel(
    const float* __restrict__ query, const float* __restrict__ keys,
    const float* __restrict__ Wq,    const float* __restrict__ Wk,
    const float* __restrict__ bk)
{
    __shared__ float in_sh[8][DIN_];

    const int blk = blockIdx.x;            // 0..287
    const bool isQ = (blk < 32);
    const int r0 = (isQ ? blk : (blk - 32)) * 8;
    const float* __restrict__ in = isQ ? query : keys;
    const float* __restrict__ W  = isQ ? Wq    : Wk;
    float* __restrict__ outb     = isQ ? g_Q   : g_K;

    const int tid = threadIdx.x;
    const int cg = tid & 63;                // cols 4*cg..4*cg+3
    const int rg = tid >> 6;                // rows rg*2, rg*2+1

    if (tid < 128) {
        const int r = tid >> 4, s = tid & 15;
        *(float4*)&in_sh[r][s * 4] =
            *(const float4*)(in + (size_t)(r0 + r) * DIN_ + s * 4);
    }
    __syncthreads();

    float4 bias = make_float4(0.f, 0.f, 0.f, 0.f);
    if (!isQ) bias = *(const float4*)(bk + cg * 4);

    float4 acc0 = bias, acc1 = bias;
    const int row0 = rg * 2, row1 = rg * 2 + 1;

    float4 wcur[8], wnxt[8];
#pragma unroll
    for (int i = 0; i < 8; i++)
        wcur[i] = *(const float4*)(W + (size_t)i * DOUT_ + cg * 4);

#pragma unroll
    for (int ic = 0; ic < 8; ic++) {
        if (ic < 7) {
#pragma unroll
            for (int i = 0; i < 8; i++)
                wnxt[i] = *(const float4*)(W + (size_t)((ic + 1) * 8 + i) * DOUT_ + cg * 4);
        }
#pragma unroll
        for (int i = 0; i < 8; i++) {
            const float x0 = in_sh[row0][ic * 8 + i];
            const float x1 = in_sh[row1][ic * 8 + i];
            acc0.x = fmaf(x0, wcur[i].x, acc0.x);
            acc0.y = fmaf(x0, wcur[i].y, acc0.y);
            acc0.z = fmaf(x0, wcur[i].z, acc0.z);
            acc0.w = fmaf(x0, wcur[i].w, acc0.w);
            acc1.x = fmaf(x1, wcur[i].x, acc1.x);
            acc1.y = fmaf(x1, wcur[i].y, acc1.y);
            acc1.z = fmaf(x1, wcur[i].z, acc1.z);
            acc1.w = fmaf(x1, wcur[i].w, acc1.w);
        }
#pragma unroll
        for (int i = 0; i < 8; i++) wcur[i] = wnxt[i];
    }

    *(float4*)&outb[(size_t)(r0 + row0) * DOUT_ + cg * 4] = acc0;
    *(float4*)&outb[(size_t)(r0 + row1) * DOUT_ + cg * 4] = acc1;
}

// ---------------------------------------------------------------------------
// Kernel 2: partial scores over a d-half, fp32 + tanh.approx.f32.
// Grid = 16 bt x 16 qc x 2 dh = 512 blocks x 256 thr (one wave, 4 blocks/SM
// -> 32 warps/SM). Warp w -> q row qc*8+w; lane owns nk {l,l+32,l+64,l+96}.
// d-half processed as 2 staged chunks of 64 d. MUFU-bound by design:
// 1 MUFU.TANH per element, floor ~28.3K cyc/SM.
// ---------------------------------------------------------------------------
__global__ void __launch_bounds__(256, 4) attn_partial_kernel(
    const float* __restrict__ v)
{
    __shared__ float k_sh[NK_ * KPITCH_];      // 34.8 KB
    __shared__ float q_sh[8][DC_];             // 2 KB
    __shared__ float v_sh[DC_];                // 256 B

    const int blk = blockIdx.x;
    const int dh  = blk & 1;
    const int qc  = (blk >> 1) & 15;
    const int bt  = blk >> 5;
    const int b   = bt >> 3;

    const int tid  = threadIdx.x;
    const int w    = tid >> 5;
    const int lane = tid & 31;

    float accA = 0.f, accB = 0.f, accC = 0.f, accD = 0.f;

#pragma unroll 1
    for (int c = 0; c < DH_ / DC_; c++) {
        const int d0 = dh * DH_ + c * DC_;     // offset within DOUT_
        const float* __restrict__ kbase = g_K + (size_t)(bt * NK_) * DOUT_ + d0;
        const float* __restrict__ qbase = g_Q + (size_t)(b * NQ_ + qc * 8) * DOUT_ + d0;

        // Stage K chunk: 128 rows x 16 float4 (8 per thread), pitch 68 words
#pragma unroll
        for (int e = tid; e < NK_ * 16; e += 256) {
            const int nk = e >> 4, s = e & 15;
            float4 t = *(const float4*)(kbase + (size_t)nk * DOUT_ + s * 4);
            *(float4*)&k_sh[nk * KPITCH_ + s * 4] = t;
        }
        // Stage Q chunk: 8 rows x 16 float4
        if (tid < 128) {
            const int r = tid >> 4, s = tid & 15;
            *(float4*)&q_sh[r][s * 4] =
                *(const float4*)(qbase + (size_t)r * DOUT_ + s * 4);
        }
        // Stage v chunk
        if (tid >= 128 && tid < 144) {
            const int s = tid - 128;
            *(float4*)&v_sh[s * 4] = *(const float4*)(v + d0 + s * 4);
        }
        __syncthreads();

        const float* __restrict__ kAp = &k_sh[(lane      ) * KPITCH_];
        const float* __restrict__ kBp = &k_sh[(lane + 32 ) * KPITCH_];
        const float* __restrict__ kCp = &k_sh[(lane + 64 ) * KPITCH_];
        const float* __restrict__ kDp = &k_sh[(lane + 96 ) * KPITCH_];

#pragma unroll 4
        for (int d4 = 0; d4 < DC_; d4 += 4) {
            // Front-load this 4-d group: 6 x LDS.128
            float4 kA = *(const float4*)(kAp + d4);
            float4 kB = *(const float4*)(kBp + d4);
            float4 kC = *(const float4*)(kCp + d4);
            float4 kD = *(const float4*)(kDp + d4);
            float4 qv = *(const float4*)&q_sh[w][d4];
            float4 vv = *(const float4*)&v_sh[d4];

            accA = fmaf(vv.x, ftanh(qv.x + kA.x), accA);
            accB = fmaf(vv.x, ftanh(qv.x + kB.x), accB);
            accC = fmaf(vv.x, ftanh(qv.x + kC.x), accC);
            accD = fmaf(vv.x, ftanh(qv.x + kD.x), accD);

            accA = fmaf(vv.y, ftanh(qv.y + kA.y), accA);
            accB = fmaf(vv.y, ftanh(qv.y + kB.y), accB);
            accC = fmaf(vv.y, ftanh(qv.y + kC.y), accC);
            accD = fmaf(vv.y, ftanh(qv.y + kD.y), accD);

            accA = fmaf(vv.z, ftanh(qv.z + kA.z), accA);
            accB = fmaf(vv.z, ftanh(qv.z + kB.z), accB);
            accC = fmaf(vv.z, ftanh(qv.z + kC.z), accC);
            accD = fmaf(vv.z, ftanh(qv.z + kD.z), accD);

            accA = fmaf(vv.w, ftanh(qv.w + kA.w), accA);
            accB = fmaf(vv.w, ftanh(qv.w + kB.w), accB);
            accC = fmaf(vv.w, ftanh(qv.w + kC.w), accC);
            accD = fmaf(vv.w, ftanh(qv.w + kD.w), accD);
        }
        __syncthreads();
    }

    // Write partials: g_P[dh][bt][q][nk], coalesced 32-lane groups
    float* __restrict__ prow =
        g_P + ((size_t)dh * BT_ * NQ_ + (size_t)(bt * NQ_ + qc * 8 + w)) * NK_;
    prow[lane      ] = accA;
    prow[lane + 32 ] = accB;
    prow[lane + 64 ] = accC;
    prow[lane + 96 ] = accD;
}

// ---------------------------------------------------------------------------
// Kernel 3: combine d-halves + softmax (unchanged).
// ---------------------------------------------------------------------------
__global__ void __launch_bounds__(256) combine_kernel(float* __restrict__ out)
{
    const int tid  = threadIdx.x;
    const int w    = tid >> 5;
    const int lane = tid & 31;
    const int r    = blockIdx.x * 8 + w;

    const float* __restrict__ p0 = g_P + (size_t)r * NK_;
    const float* __restrict__ p1 = g_P + (size_t)(BT_ * NQ_ + r) * NK_;

    float4 a = *(const float4*)(p0 + lane * 4);
    float4 c = *(const float4*)(p1 + lane * 4);
    float4 s = make_float4(a.x + c.x, a.y + c.y, a.z + c.z, a.w + c.w);

    float m = fmaxf(fmaxf(s.x, s.y), fmaxf(s.z, s.w));
#pragma unroll
    for (int o = 16; o > 0; o >>= 1)
        m = fmaxf(m, __shfl_xor_sync(0xffffffffu, m, o));

    float4 e = make_float4(__expf(s.x - m), __expf(s.y - m),
                           __expf(s.z - m), __expf(s.w - m));
    float ssum = e.x + e.y + e.z + e.w;
#pragma unroll
    for (int o = 16; o > 0; o >>= 1)
        ssum += __shfl_xor_sync(0xffffffffu, ssum, o);

    const float rinv = 1.0f / ssum;
    float4 res = make_float4(e.x * rinv, e.y * rinv, e.z * rinv, e.w * rinv);
    *(float4*)(out + (size_t)r * NK_ + lane * 4) = res;
}

// ---------------------------------------------------------------------------
extern "C" void kernel_launch(void* const* d_in, const int* in_sizes, int n_in,
                              void* d_out, int out_size)
{
    const float* query = (const float*)d_in[0];
    const float* keys  = (const float*)d_in[1];
    const float* Wq    = (const float*)d_in[2];
    const float* Wk    = (const float*)d_in[3];
    const float* bk    = (const float*)d_in[4];
    const float* v     = (const float*)d_in[5];
    float* out = (float*)d_out;

    proj_kernel<<<288, 256>>>(query, keys, Wq, Wk, bk);
    attn_partial_kernel<<<512, 256>>>(v);
    combine_kernel<<<256, 256>>>(out);
}